// round 11
// baseline (speedup 1.0000x reference)
#include <cuda_runtime.h>
#include <cuda_fp16.h>
#include <math.h>
#include <stdint.h>

#define NB 32
#define NS 64
#define NE 512
#define NV 50257
#define NVP 50304             // NV padded to 128
#define NTOK (NB*NS)          // 2048
#define KSEL (NS/2)           // 32
#define EPS_ATK 0.4f
#define STD_MULT 3.0
#define COS_EPS 1e-8f

// GEMM tile config
#define TC_M 128
#define TC_N 128
#define KCH 64
#define NCHUNK (NE / KCH)     // 8
#define NBLK (NVP / TC_N)     // 393
#define NSTAGE 3

// ---------------- scratch (device globals; no allocation allowed) ----------
__device__ __half d_pertH[NTOK*NE];      // 2 MB
__device__ __half d_embH[NVP*NE];        // 51.5 MB
__device__ int    d_mask[NTOK];
__device__ float  d_pinv[NTOK];
__device__ float  d_tinv[NV];
__device__ double d_bsum[NB];
__device__ double d_bsumsq[NB];
__device__ unsigned long long d_best[NTOK];
__device__ int    d_cnt[NTOK];

// ---------------- PTX helpers (baseline ISA only) ---------------------------
__device__ __forceinline__ uint32_t smem_u32(const void* p) {
    uint32_t a;
    asm("{ .reg .u64 t; cvta.to.shared.u64 t, %1; cvt.u32.u64 %0, t; }"
        : "=r"(a) : "l"(p));
    return a;
}
__device__ __forceinline__ void cp_async16(uint32_t dst, const void* src) {
    asm volatile("cp.async.cg.shared.global [%0], [%1], 16;"
                 :: "r"(dst), "l"(src) : "memory");
}
__device__ __forceinline__ void cp_commit() {
    asm volatile("cp.async.commit_group;" ::: "memory");
}
template<int N> __device__ __forceinline__ void cp_wait() {
    asm volatile("cp.async.wait_group %0;" :: "n"(N) : "memory");
}
__device__ __forceinline__ void ldmat4(uint32_t& r0, uint32_t& r1, uint32_t& r2,
                                       uint32_t& r3, uint32_t addr) {
    asm volatile("ldmatrix.sync.aligned.m8n8.x4.shared.b16 {%0,%1,%2,%3}, [%4];"
                 : "=r"(r0), "=r"(r1), "=r"(r2), "=r"(r3) : "r"(addr));
}
__device__ __forceinline__ void mma_f16(float* d, const uint32_t* a, const uint32_t* b) {
    asm volatile(
        "mma.sync.aligned.m16n8k16.row.col.f32.f16.f16.f32 "
        "{%0,%1,%2,%3}, {%4,%5,%6,%7}, {%8,%9}, {%0,%1,%2,%3};"
        : "+f"(d[0]), "+f"(d[1]), "+f"(d[2]), "+f"(d[3])
        : "r"(a[0]), "r"(a[1]), "r"(a[2]), "r"(a[3]), "r"(b[0]), "r"(b[1]));
}

// argmax key: monotone float encoding, ~index for smaller-index-wins on ties
static __device__ __forceinline__ unsigned long long packKey(float v, int n) {
    unsigned u = __float_as_uint(v);
    u = (u & 0x80000000u) ? ~u : (u | 0x80000000u);
    return ((unsigned long long)u << 32) | (unsigned)(~n);
}

// ---------------- K1: fused prep ------------------------------------------
// Blocks [0, NVP): emb fp16 convert + vocab row inv-norm (128 thr, 1 f4 each)
// Blocks [NVP, NVP+NB): per-batch |grad| sums -> top-k mask -> masked stats
__global__ void k_prep(const float* __restrict__ emb,
                       const float* __restrict__ grad) {
    const int tid = threadIdx.x, lane = tid & 31, w = tid >> 5;
    if (blockIdx.x < NVP) {
        int row = blockIdx.x;
        float4 v = make_float4(0.f, 0.f, 0.f, 0.f);
        if (row < NV)
            v = __ldg((const float4*)(emb + (size_t)row * NE) + tid);
        __half h0 = __float2half(v.x), h1 = __float2half(v.y);
        __half h2 = __float2half(v.z), h3 = __float2half(v.w);
        uint2 hv;
        hv.x = (uint32_t)__half_as_ushort(h0) | ((uint32_t)__half_as_ushort(h1) << 16);
        hv.y = (uint32_t)__half_as_ushort(h2) | ((uint32_t)__half_as_ushort(h3) << 16);
        ((uint2*)(d_embH + (size_t)row * NE))[tid] = hv;
        float acc = v.x * v.x + v.y * v.y + v.z * v.z + v.w * v.w;
        __shared__ float sh[4];
        #pragma unroll
        for (int o = 16; o > 0; o >>= 1) acc += __shfl_down_sync(0xffffffffu, acc, o);
        if (lane == 0) sh[w] = acc;
        __syncthreads();
        if (tid == 0 && row < NV) {
            float s = sh[0] + sh[1] + sh[2] + sh[3];
            d_tinv[row] = 1.f / fmaxf(sqrtf(s), COS_EPS);
        }
    } else {
        int b = blockIdx.x - NVP;
        __shared__ float s_absg[NS];
        __shared__ int s_msk[NS];
        __shared__ double s_d[8];
        // pass 1: warp w handles tokens w, w+4, ... (16 tokens each)
        for (int tok = w; tok < NS; tok += 4) {
            const float4* p = (const float4*)(grad + (size_t)(b * NS + tok) * NE);
            float s = 0.f;
            #pragma unroll 4
            for (int i = lane; i < NE / 4; i += 32) {
                float4 v = p[i];
                s += fabsf(v.x) + fabsf(v.y) + fabsf(v.z) + fabsf(v.w);
            }
            #pragma unroll
            for (int o = 16; o > 0; o >>= 1) s += __shfl_down_sync(0xffffffffu, s, o);
            if (lane == 0) s_absg[tok] = s;
        }
        __syncthreads();
        // top-k mask by rank count (stable ties)
        if (tid < NS) {
            float me = s_absg[tid];
            int rank = 0;
            #pragma unroll 8
            for (int j = 0; j < NS; j++)
                rank += (s_absg[j] > me) || (s_absg[j] == me && j < tid);
            int mk = (rank < KSEL) ? 1 : 0;
            s_msk[tid] = mk;
            d_mask[b * NS + tid] = mk;
        }
        __syncthreads();
        // pass 2: masked sum / sumsq (L2-hot re-read, double accum)
        double s = 0.0, s2 = 0.0;
        for (int tok = w; tok < NS; tok += 4) {
            if (!s_msk[tok]) continue;
            const float4* p = (const float4*)(grad + (size_t)(b * NS + tok) * NE);
            #pragma unroll 4
            for (int i = lane; i < NE / 4; i += 32) {
                float4 v = p[i];
                double x;
                x = v.x; s += x; s2 += x * x;
                x = v.y; s += x; s2 += x * x;
                x = v.z; s += x; s2 += x * x;
                x = v.w; s += x; s2 += x * x;
            }
        }
        #pragma unroll
        for (int o = 16; o > 0; o >>= 1) {
            s  += __shfl_down_sync(0xffffffffu, s,  o);
            s2 += __shfl_down_sync(0xffffffffu, s2, o);
        }
        if (lane == 0) { s_d[w] = s; s_d[4 + w] = s2; }
        __syncthreads();
        if (tid == 0) {
            d_bsum[b]   = s_d[0] + s_d[1] + s_d[2] + s_d[3];
            d_bsumsq[b] = s_d[4] + s_d[5] + s_d[6] + s_d[7];
        }
    }
}

// ---------------- K2: perturb + inv norm + fp16 store + bounds ------------
__global__ void k_perturb(const int* __restrict__ utt,
                          const float* __restrict__ emb,
                          const float* __restrict__ grad) {
    __shared__ float s_bounds[2];
    __shared__ float sh[4];
    const int tid = threadIdx.x, lane = tid & 31, w = tid >> 5;
    const int t = blockIdx.x;
    // redundant per-block bounds computation from 32 batch partials
    if (w == 0) {
        double s = d_bsum[lane], s2 = d_bsumsq[lane];
        #pragma unroll
        for (int o = 16; o > 0; o >>= 1) {
            s  += __shfl_down_sync(0xffffffffu, s,  o);
            s2 += __shfl_down_sync(0xffffffffu, s2, o);
        }
        if (lane == 0) {
            double n = (double)NB * KSEL * NE;
            double mean = s / n;
            double var = (s2 - n * mean * mean) / (n - 1.0);
            double sd = sqrt(var);
            s_bounds[0] = (float)(mean - sd * STD_MULT);
            s_bounds[1] = (float)(mean + sd * STD_MULT);
            d_best[t] = 0ull;
            d_cnt[t] = 0;
        }
    }
    __syncthreads();
    const float lb = s_bounds[0], ub = s_bounds[1];
    const int u = utt[t];
    const int m = d_mask[t];
    const float* erow = emb + (size_t)u * NE;
    const float* grow = grad + (size_t)t * NE;
    __half* hrow = d_pertH + (size_t)t * NE;
    float acc = 0.f;
    for (int e = tid; e < NE; e += blockDim.x) {
        float ev = erow[e];
        float dg = grow[e];
        float p = ev;
        if (m && (dg < lb || dg > ub))
            p += (dg > 0.f) ? EPS_ATK : ((dg < 0.f) ? -EPS_ATK : 0.f);
        hrow[e] = __float2half(p);
        acc += p * p;
    }
    #pragma unroll
    for (int o = 16; o > 0; o >>= 1) acc += __shfl_down_sync(0xffffffffu, acc, o);
    if (lane == 0) sh[w] = acc;
    __syncthreads();
    if (tid == 0) {
        float s = sh[0] + sh[1] + sh[2] + sh[3];
        d_pinv[t] = 1.f / fmaxf(sqrtf(s), COS_EPS);
    }
}

// ---------------- K3: HMMA fp16 GEMM, 3-stage pipe, fused epilogue --------
#define PLANE 16384
#define STG_BYTES (2*PLANE)   // 32KB per stage

__global__ __launch_bounds__(256, 2) void k_gemm(float* __restrict__ simOut,
                                                 float* __restrict__ nnOut) {
    extern __shared__ char dsm[];
    __shared__ float s_tinv[TC_N];
    __shared__ float s_pinv[TC_M];

    const int tid = threadIdx.x;
    const int lane = tid & 31;
    const int wid = tid >> 5;
    const int warp_m = wid & 3;        // 4 row groups of 32
    const int warp_n = wid >> 2;       // 2 col groups of 64
    const int col0 = blockIdx.x * TC_N;
    const int row0 = blockIdx.y * TC_M;

    if (tid < TC_M) s_pinv[tid] = d_pinv[row0 + tid];
    if (tid < TC_N) {
        int c = col0 + tid;
        s_tinv[tid] = (c < NV) ? d_tinv[c] : 0.f;
    }

    const uint32_t smemBase = smem_u32(dsm);

    auto loadStage = [&](int ch, int buf) {
        const int k0 = ch * KCH;
        uint32_t sb = smemBase + buf * STG_BYTES;
        #pragma unroll
        for (int i = 0; i < 4; i++) {
            int q = i * 256 + tid;
            int r = q >> 3, c = q & 7;
            uint32_t dst = sb + r * 128 + ((c ^ (r & 7)) << 4);
            cp_async16(dst,         d_pertH + (size_t)(row0 + r) * NE + k0 + c * 8);
            cp_async16(dst + PLANE, d_embH  + (size_t)(col0 + r) * NE + k0 + c * 8);
        }
    };

    float acc[2][8][4];
    #pragma unroll
    for (int i = 0; i < 2; i++)
        #pragma unroll
        for (int j = 0; j < 8; j++)
            #pragma unroll
            for (int k = 0; k < 4; k++) acc[i][j][k] = 0.f;

    const int aRowIn = lane & 15;
    const int aSel = lane >> 4;
    const int bRowIn = (lane & 7) + ((lane >> 4) << 3);
    const int bSel = (lane >> 3) & 1;

    loadStage(0, 0); cp_commit();
    loadStage(1, 1); cp_commit();

    for (int ch = 0; ch < NCHUNK; ch++) {
        if (ch < NCHUNK - 1) cp_wait<1>(); else cp_wait<0>();
        __syncthreads();   // stage ch ready; all warps done with buf (ch-1)%3
        if (ch + 2 < NCHUNK) { loadStage(ch + 2, (ch + 2) % NSTAGE); cp_commit(); }
        const uint32_t sb = smemBase + (ch % NSTAGE) * STG_BYTES;

        #pragma unroll
        for (int ks = 0; ks < 4; ks++) {
            uint32_t Ah[2][4], Bh[4][4];
            #pragma unroll
            for (int im = 0; im < 2; im++) {
                int row = warp_m * 32 + im * 16 + aRowIn;
                uint32_t off = row * 128 + (((ks * 2 + aSel) ^ (row & 7)) << 4);
                ldmat4(Ah[im][0], Ah[im][1], Ah[im][2], Ah[im][3], sb + off);
            }
            #pragma unroll
            for (int jn = 0; jn < 4; jn++) {
                int nr = warp_n * 64 + jn * 16 + bRowIn;
                uint32_t off = nr * 128 + (((ks * 2 + bSel) ^ (nr & 7)) << 4);
                ldmat4(Bh[jn][0], Bh[jn][1], Bh[jn][2], Bh[jn][3], sb + PLANE + off);
            }
            #pragma unroll
            for (int im = 0; im < 2; im++)
                #pragma unroll
                for (int jn = 0; jn < 4; jn++) {
                    mma_f16(acc[im][2 * jn],     Ah[im], &Bh[jn][0]);
                    mma_f16(acc[im][2 * jn + 1], Ah[im], &Bh[jn][2]);
                }
        }
    }

    // ---- register-direct epilogue: scale, scalar streaming stores, argmax
    // (scalar STG.32 only: row base simOut + r*NV has 4B alignment since NV
    //  is odd — a float2 store here traps with misaligned address)
    const int rb = lane >> 2, cb = (lane & 3) * 2;
    #pragma unroll
    for (int im = 0; im < 2; im++) {
        #pragma unroll
        for (int kh = 0; kh < 2; kh++) {
            const int r = warp_m * 32 + im * 16 + rb + kh * 8;
            const float pi = s_pinv[r];
            float* orow = simOut + (size_t)(row0 + r) * NV;
            float bv = -1e30f;
            int bn = -1;
            #pragma unroll
            for (int jn = 0; jn < 8; jn++) {
                const int c = warp_n * 64 + jn * 8 + cb;
                const int gc = col0 + c;
                float v0 = acc[im][jn][kh * 2]     * pi * s_tinv[c];
                float v1 = acc[im][jn][kh * 2 + 1] * pi * s_tinv[c + 1];
                if (gc < NV) {
                    __stcs(orow + gc, v0);
                    if (v0 > bv) { bv = v0; bn = gc; }
                }
                if (gc + 1 < NV) {
                    __stcs(orow + gc + 1, v1);
                    if (v1 > bv) { bv = v1; bn = gc + 1; }
                }
            }
            if (nnOut) {
                unsigned long long key = (bn >= 0) ? packKey(bv, bn) : 0ull;
                unsigned long long o1 = __shfl_xor_sync(0xffffffffu, key, 1);
                if (o1 > key) key = o1;
                unsigned long long o2 = __shfl_xor_sync(0xffffffffu, key, 2);
                if (o2 > key) key = o2;
                if ((lane & 3) == 0) {
                    const int rowg = row0 + r;
                    if (key) atomicMax(&d_best[rowg], key);
                    __threadfence();
                    int c = atomicAdd(&d_cnt[rowg], 1);
                    if (c == 2 * NBLK - 1) {     // last arrival: decode
                        __threadfence();
                        unsigned long long b =
                            *(volatile unsigned long long*)&d_best[rowg];
                        nnOut[rowg] = (float)(~(unsigned)(b & 0xFFFFFFFFull));
                    }
                }
            }
        }
    }
}

// ---------------- launch ---------------------------------------------------
extern "C" void kernel_launch(void* const* d_in, const int* in_sizes, int n_in,
                              void* d_out, int out_size) {
    const int* utt = (const int*)d_in[0];     // [B,S] int32
    const float* emb = (const float*)d_in[1]; // [V,E] fp32
    const float* grad = (const float*)d_in[2];// [B,S,E] fp32
    float* out = (float*)d_out;

    float* nnOut = nullptr;
    float* simOut = out;
    if (out_size == NTOK * (NV + 1)) {        // tuple order: nn_idx, then sim
        nnOut = out;
        simOut = out + NTOK;
    }

    k_prep<<<NVP + NB, 128>>>(emb, grad);
    k_perturb<<<NTOK, 128>>>(utt, emb, grad);

    const int dynSmem = NSTAGE * STG_BYTES;   // 96KB
    static int attrSet = 0;
    if (!attrSet) {
        cudaFuncSetAttribute(k_gemm, cudaFuncAttributeMaxDynamicSharedMemorySize, dynSmem);
        attrSet = 1;
    }
    dim3 g(NBLK, NTOK / TC_M);
    k_gemm<<<g, 256, dynSmem>>>(simOut, nnOut);
}

// round 12
// speedup vs baseline: 1.1799x; 1.1799x over previous
#include <cuda_runtime.h>
#include <cuda_fp16.h>
#include <math.h>
#include <stdint.h>

#define NB 32
#define NS 64
#define NE 512
#define NV 50257
#define NVP 50304             // NV padded to 128
#define NTOK (NB*NS)          // 2048
#define KSEL (NS/2)           // 32
#define EPS_ATK 0.4f
#define STD_MULT 3.0
#define COS_EPS 1e-8f

// GEMM tile config
#define TC_M 128
#define TC_N 128
#define KCH 64
#define NCHUNK (NE / KCH)     // 8
#define NBLK (NVP / TC_N)     // 393
#define ROWS_PER_BLK 8
#define NVB (NVP / ROWS_PER_BLK)   // 6288 emb-convert blocks

// ---------------- scratch (device globals; no allocation allowed) ----------
__device__ __half d_pertH[NTOK*NE];      // 2 MB
__device__ __half d_embH[NVP*NE];        // 51.5 MB
__device__ int    d_mask[NTOK];
__device__ float  d_pinv[NTOK];
__device__ float  d_tinv[NV];
__device__ double d_bsum[NB];
__device__ double d_bsumsq[NB];
__device__ unsigned long long d_best[NTOK];

// ---------------- PTX helpers (baseline ISA only) ---------------------------
__device__ __forceinline__ uint32_t smem_u32(const void* p) {
    uint32_t a;
    asm("{ .reg .u64 t; cvta.to.shared.u64 t, %1; cvt.u32.u64 %0, t; }"
        : "=r"(a) : "l"(p));
    return a;
}
__device__ __forceinline__ void cp_async16(uint32_t dst, const void* src) {
    asm volatile("cp.async.cg.shared.global [%0], [%1], 16;"
                 :: "r"(dst), "l"(src) : "memory");
}
__device__ __forceinline__ void cp_commit() {
    asm volatile("cp.async.commit_group;" ::: "memory");
}
template<int N> __device__ __forceinline__ void cp_wait() {
    asm volatile("cp.async.wait_group %0;" :: "n"(N) : "memory");
}
__device__ __forceinline__ void ldmat4(uint32_t& r0, uint32_t& r1, uint32_t& r2,
                                       uint32_t& r3, uint32_t addr) {
    asm volatile("ldmatrix.sync.aligned.m8n8.x4.shared.b16 {%0,%1,%2,%3}, [%4];"
                 : "=r"(r0), "=r"(r1), "=r"(r2), "=r"(r3) : "r"(addr));
}
__device__ __forceinline__ void mma_f16(float* d, const uint32_t* a, const uint32_t* b) {
    asm volatile(
        "mma.sync.aligned.m16n8k16.row.col.f32.f16.f16.f32 "
        "{%0,%1,%2,%3}, {%4,%5,%6,%7}, {%8,%9}, {%0,%1,%2,%3};"
        : "+f"(d[0]), "+f"(d[1]), "+f"(d[2]), "+f"(d[3])
        : "r"(a[0]), "r"(a[1]), "r"(a[2]), "r"(a[3]), "r"(b[0]), "r"(b[1]));
}

// argmax key: monotone float encoding, ~index for smaller-index-wins on ties
static __device__ __forceinline__ unsigned long long packKey(float v, int n) {
    unsigned u = __float_as_uint(v);
    u = (u & 0x80000000u) ? ~u : (u | 0x80000000u);
    return ((unsigned long long)u << 32) | (unsigned)(~n);
}

// ---------------- K1: fused prep ------------------------------------------
// Blocks [0, NVB): emb fp16 convert + row inv-norm; 1 warp/row, 8 rows/block,
//                  4 independent float4 loads per lane (MLP=4).
// Blocks [NVB, NVB+NB): per-batch |grad| sums -> top-k mask -> masked stats
__global__ __launch_bounds__(256) void k_prep(const float* __restrict__ emb,
                                              const float* __restrict__ grad) {
    const int tid = threadIdx.x, lane = tid & 31, w = tid >> 5;
    if (blockIdx.x < NVB) {
        const int row = blockIdx.x * ROWS_PER_BLK + w;   // warp-private row
        const bool live = row < NV;
        const float4* src = (const float4*)(emb + (size_t)row * NE);
        float4 v0, v1, v2, v3;
        if (live) {                       // 4 independent loads, front-batched
            v0 = __ldg(src + lane);
            v1 = __ldg(src + lane + 32);
            v2 = __ldg(src + lane + 64);
            v3 = __ldg(src + lane + 96);
        } else {
            v0 = v1 = v2 = v3 = make_float4(0.f, 0.f, 0.f, 0.f);
        }
        uint2* dst = (uint2*)(d_embH + (size_t)row * NE);
        float acc = 0.f;
        float4 vv[4] = {v0, v1, v2, v3};
        #pragma unroll
        for (int i = 0; i < 4; i++) {
            float4 v = vv[i];
            __half h0 = __float2half(v.x), h1 = __float2half(v.y);
            __half h2 = __float2half(v.z), h3 = __float2half(v.w);
            uint2 hv;
            hv.x = (uint32_t)__half_as_ushort(h0) | ((uint32_t)__half_as_ushort(h1) << 16);
            hv.y = (uint32_t)__half_as_ushort(h2) | ((uint32_t)__half_as_ushort(h3) << 16);
            dst[lane + i * 32] = hv;
            acc += v.x * v.x + v.y * v.y + v.z * v.z + v.w * v.w;
        }
        #pragma unroll
        for (int o = 16; o > 0; o >>= 1) acc += __shfl_down_sync(0xffffffffu, acc, o);
        if (lane == 0 && live)
            d_tinv[row] = 1.f / fmaxf(sqrtf(acc), COS_EPS);
    } else {
        const int b = blockIdx.x - NVB;
        __shared__ float s_absg[NS];
        __shared__ int s_msk[NS];
        __shared__ double s_d[16];
        // pass 1: warp w handles tokens w, w+8, ... (8 tokens each)
        for (int tok = w; tok < NS; tok += 8) {
            const float4* p = (const float4*)(grad + (size_t)(b * NS + tok) * NE);
            float s = 0.f;
            #pragma unroll 4
            for (int i = lane; i < NE / 4; i += 32) {
                float4 v = p[i];
                s += fabsf(v.x) + fabsf(v.y) + fabsf(v.z) + fabsf(v.w);
            }
            #pragma unroll
            for (int o = 16; o > 0; o >>= 1) s += __shfl_down_sync(0xffffffffu, s, o);
            if (lane == 0) s_absg[tok] = s;
        }
        __syncthreads();
        // top-k mask by rank count (stable ties)
        if (tid < NS) {
            float me = s_absg[tid];
            int rank = 0;
            #pragma unroll 8
            for (int j = 0; j < NS; j++)
                rank += (s_absg[j] > me) || (s_absg[j] == me && j < tid);
            int mk = (rank < KSEL) ? 1 : 0;
            s_msk[tid] = mk;
            d_mask[b * NS + tid] = mk;
        }
        __syncthreads();
        // pass 2: masked sum / sumsq (L2-hot re-read, double accum)
        double s = 0.0, s2 = 0.0;
        for (int tok = w; tok < NS; tok += 8) {
            if (!s_msk[tok]) continue;
            const float4* p = (const float4*)(grad + (size_t)(b * NS + tok) * NE);
            #pragma unroll 4
            for (int i = lane; i < NE / 4; i += 32) {
                float4 v = p[i];
                double x;
                x = v.x; s += x; s2 += x * x;
                x = v.y; s += x; s2 += x * x;
                x = v.z; s += x; s2 += x * x;
                x = v.w; s += x; s2 += x * x;
            }
        }
        #pragma unroll
        for (int o = 16; o > 0; o >>= 1) {
            s  += __shfl_down_sync(0xffffffffu, s,  o);
            s2 += __shfl_down_sync(0xffffffffu, s2, o);
        }
        if (lane == 0) { s_d[w] = s; s_d[8 + w] = s2; }
        __syncthreads();
        if (tid == 0) {
            double ts = 0.0, ts2 = 0.0;
            #pragma unroll
            for (int i = 0; i < 8; i++) { ts += s_d[i]; ts2 += s_d[8 + i]; }
            d_bsum[b] = ts;
            d_bsumsq[b] = ts2;
        }
    }
}

// ---------------- K2: perturb + inv norm + fp16 store + bounds ------------
__global__ void k_perturb(const int* __restrict__ utt,
                          const float* __restrict__ emb,
                          const float* __restrict__ grad) {
    __shared__ float s_bounds[2];
    __shared__ float sh[4];
    const int tid = threadIdx.x, lane = tid & 31, w = tid >> 5;
    const int t = blockIdx.x;
    // redundant per-block bounds computation from 32 batch partials
    if (w == 0) {
        double s = d_bsum[lane], s2 = d_bsumsq[lane];
        #pragma unroll
        for (int o = 16; o > 0; o >>= 1) {
            s  += __shfl_down_sync(0xffffffffu, s,  o);
            s2 += __shfl_down_sync(0xffffffffu, s2, o);
        }
        if (lane == 0) {
            double n = (double)NB * KSEL * NE;
            double mean = s / n;
            double var = (s2 - n * mean * mean) / (n - 1.0);
            double sd = sqrt(var);
            s_bounds[0] = (float)(mean - sd * STD_MULT);
            s_bounds[1] = (float)(mean + sd * STD_MULT);
            d_best[t] = 0ull;
        }
    }
    __syncthreads();
    const float lb = s_bounds[0], ub = s_bounds[1];
    const int u = utt[t];
    const int m = d_mask[t];
    const float* erow = emb + (size_t)u * NE;
    const float* grow = grad + (size_t)t * NE;
    __half* hrow = d_pertH + (size_t)t * NE;
    float acc = 0.f;
    for (int e = tid; e < NE; e += blockDim.x) {
        float ev = erow[e];
        float dg = grow[e];
        float p = ev;
        if (m && (dg < lb || dg > ub))
            p += (dg > 0.f) ? EPS_ATK : ((dg < 0.f) ? -EPS_ATK : 0.f);
        hrow[e] = __float2half(p);
        acc += p * p;
    }
    #pragma unroll
    for (int o = 16; o > 0; o >>= 1) acc += __shfl_down_sync(0xffffffffu, acc, o);
    if (lane == 0) sh[w] = acc;
    __syncthreads();
    if (tid == 0) {
        float s = sh[0] + sh[1] + sh[2] + sh[3];
        d_pinv[t] = 1.f / fmaxf(sqrtf(s), COS_EPS);
    }
}

// ---------------- K3: HMMA fp16 GEMM (R10-proven 2-stage) + epilogue ------
#define PLANE 16384
#define STG_BYTES (2*PLANE)   // 32KB per stage

__global__ __launch_bounds__(256, 2) void k_gemm(float* __restrict__ simOut,
                                                 int doArgmax) {
    extern __shared__ char dsm[];
    __shared__ float s_tinv[TC_N];
    __shared__ float s_pinv[TC_M];

    const int tid = threadIdx.x;
    const int wid = tid >> 5;
    const int lane = tid & 31;
    const int warp_m = wid & 3;        // 4 row groups of 32
    const int warp_n = wid >> 2;       // 2 col groups of 64
    const int col0 = blockIdx.x * TC_N;
    const int row0 = blockIdx.y * TC_M;

    if (tid < TC_M) s_pinv[tid] = d_pinv[row0 + tid];
    if (tid < TC_N) {
        int c = col0 + tid;
        s_tinv[tid] = (c < NV) ? d_tinv[c] : 0.f;
    }

    const uint32_t smemBase = smem_u32(dsm);

    auto loadStage = [&](int ch, int buf) {
        const int k0 = ch * KCH;
        uint32_t sb = smemBase + buf * STG_BYTES;
        #pragma unroll
        for (int i = 0; i < 4; i++) {
            int q = i * 256 + tid;
            int r = q >> 3, c = q & 7;
            uint32_t dst = sb + r * 128 + ((c ^ (r & 7)) << 4);
            cp_async16(dst,         d_pertH + (size_t)(row0 + r) * NE + k0 + c * 8);
            cp_async16(dst + PLANE, d_embH  + (size_t)(col0 + r) * NE + k0 + c * 8);
        }
    };

    float acc[2][8][4];
    #pragma unroll
    for (int i = 0; i < 2; i++)
        #pragma unroll
        for (int j = 0; j < 8; j++)
            #pragma unroll
            for (int k = 0; k < 4; k++) acc[i][j][k] = 0.f;

    const int aRowIn = lane & 15;
    const int aSel = lane >> 4;
    const int bRowIn = (lane & 7) + ((lane >> 4) << 3);
    const int bSel = (lane >> 3) & 1;

    loadStage(0, 0); cp_commit();
    loadStage(1, 1); cp_commit();

    for (int ch = 0; ch < NCHUNK; ch++) {
        if (ch < NCHUNK - 1) cp_wait<1>(); else cp_wait<0>();
        __syncthreads();
        const uint32_t sb = smemBase + (ch & 1) * STG_BYTES;

        #pragma unroll
        for (int ks = 0; ks < 4; ks++) {
            uint32_t Ah[2][4], Bh[4][4];
            #pragma unroll
            for (int im = 0; im < 2; im++) {
                int row = warp_m * 32 + im * 16 + aRowIn;
                uint32_t off = row * 128 + (((ks * 2 + aSel) ^ (row & 7)) << 4);
                ldmat4(Ah[im][0], Ah[im][1], Ah[im][2], Ah[im][3], sb + off);
            }
            #pragma unroll
            for (int jn = 0; jn < 4; jn++) {
                int nr = warp_n * 64 + jn * 16 + bRowIn;
                uint32_t off = nr * 128 + (((ks * 2 + bSel) ^ (nr & 7)) << 4);
                ldmat4(Bh[jn][0], Bh[jn][1], Bh[jn][2], Bh[jn][3], sb + PLANE + off);
            }
            #pragma unroll
            for (int im = 0; im < 2; im++)
                #pragma unroll
                for (int jn = 0; jn < 4; jn++) {
                    mma_f16(acc[im][2 * jn],     Ah[im], &Bh[jn][0]);
                    mma_f16(acc[im][2 * jn + 1], Ah[im], &Bh[jn][2]);
                }
        }
        __syncthreads();
        if (ch + 2 < NCHUNK) { loadStage(ch + 2, ch & 1); cp_commit(); }
    }

    // ---- register-direct epilogue: scale, scalar streaming stores, argmax
    // (scalar STG.32 only: row base simOut + r*NV has 4B alignment since NV
    //  is odd — a float2 store here traps with misaligned address)
    const int rb = lane >> 2, cb = (lane & 3) * 2;
    #pragma unroll
    for (int im = 0; im < 2; im++) {
        #pragma unroll
        for (int kh = 0; kh < 2; kh++) {
            const int r = warp_m * 32 + im * 16 + rb + kh * 8;
            const float pi = s_pinv[r];
            float* orow = simOut + (size_t)(row0 + r) * NV;
            float bv = -1e30f;
            int bn = -1;
            #pragma unroll
            for (int jn = 0; jn < 8; jn++) {
                const int c = warp_n * 64 + jn * 8 + cb;
                const int gc = col0 + c;
                float v0 = acc[im][jn][kh * 2]     * pi * s_tinv[c];
                float v1 = acc[im][jn][kh * 2 + 1] * pi * s_tinv[c + 1];
                if (gc < NV) {
                    __stcs(orow + gc, v0);
                    if (v0 > bv) { bv = v0; bn = gc; }
                }
                if (gc + 1 < NV) {
                    __stcs(orow + gc + 1, v1);
                    if (v1 > bv) { bv = v1; bn = gc + 1; }
                }
            }
            if (doArgmax) {
                unsigned long long key = (bn >= 0) ? packKey(bv, bn) : 0ull;
                unsigned long long o1 = __shfl_xor_sync(0xffffffffu, key, 1);
                if (o1 > key) key = o1;
                unsigned long long o2 = __shfl_xor_sync(0xffffffffu, key, 2);
                if (o2 > key) key = o2;
                if ((lane & 3) == 0 && key)
                    atomicMax(&d_best[row0 + r], key);
            }
        }
    }
}

// ---------------- K4: decode fused argmax ---------------------------------
__global__ void k_decode(float* __restrict__ nnOut) {
    int t = blockIdx.x * blockDim.x + threadIdx.x;
    if (t < NTOK) nnOut[t] = (float)(~(unsigned)(d_best[t] & 0xFFFFFFFFull));
}

// ---------------- launch ---------------------------------------------------
extern "C" void kernel_launch(void* const* d_in, const int* in_sizes, int n_in,
                              void* d_out, int out_size) {
    const int* utt = (const int*)d_in[0];     // [B,S] int32
    const float* emb = (const float*)d_in[1]; // [V,E] fp32
    const float* grad = (const float*)d_in[2];// [B,S,E] fp32
    float* out = (float*)d_out;

    float* nnOut = nullptr;
    float* simOut = out;
    if (out_size == NTOK * (NV + 1)) {        // tuple order: nn_idx, then sim
        nnOut = out;
        simOut = out + NTOK;
    }

    k_prep<<<NVB + NB, 256>>>(emb, grad);
    k_perturb<<<NTOK, 128>>>(utt, emb, grad);

    const int dynSmem = 2 * STG_BYTES;        // 64KB
    static int attrSet = 0;
    if (!attrSet) {
        cudaFuncSetAttribute(k_gemm, cudaFuncAttributeMaxDynamicSharedMemorySize, dynSmem);
        attrSet = 1;
    }
    dim3 g(NBLK, NTOK / TC_M);
    k_gemm<<<g, 256, dynSmem>>>(simOut, nnOut != nullptr);

    if (nnOut) k_decode<<<(NTOK + 255) / 256, 256>>>(nnOut);
}

// round 14
// speedup vs baseline: 1.1917x; 1.0100x over previous
#include <cuda_runtime.h>
#include <cuda_fp16.h>
#include <math.h>
#include <stdint.h>

#define NB 32
#define NS 64
#define NE 512
#define NV 50257
#define NVP 50304             // NV padded to 128
#define NTOK (NB*NS)          // 2048
#define KSEL (NS/2)           // 32
#define EPS_ATK 0.4f
#define STD_MULT 3.0
#define COS_EPS 1e-8f

// GEMM tile config
#define TC_M 128
#define TC_N 128
#define KCH 64
#define NCHUNK (NE / KCH)     // 8
#define NBLK (NVP / TC_N)     // 393
#define ROWS_PER_BLK 16       // 8 warps x 2 rows
#define NVB (NVP / ROWS_PER_BLK)   // 3144 emb-convert blocks

// ---------------- scratch (device globals; no allocation allowed) ----------
__device__ __half d_pertH[NTOK*NE];      // 2 MB
__device__ __half d_embH[NVP*NE];        // 51.5 MB
__device__ int    d_mask[NTOK];
__device__ float  d_pinv[NTOK];
__device__ float  d_tinv[NV];
__device__ double d_bsum[NB];
__device__ double d_bsumsq[NB];
__device__ unsigned long long d_best[NTOK];

// ---------------- PTX helpers (baseline ISA only) ---------------------------
__device__ __forceinline__ uint32_t smem_u32(const void* p) {
    uint32_t a;
    asm("{ .reg .u64 t; cvta.to.shared.u64 t, %1; cvt.u32.u64 %0, t; }"
        : "=r"(a) : "l"(p));
    return a;
}
__device__ __forceinline__ void cp_async16(uint32_t dst, const void* src) {
    asm volatile("cp.async.cg.shared.global [%0], [%1], 16;"
                 :: "r"(dst), "l"(src) : "memory");
}
__device__ __forceinline__ void cp_commit() {
    asm volatile("cp.async.commit_group;" ::: "memory");
}
template<int N> __device__ __forceinline__ void cp_wait() {
    asm volatile("cp.async.wait_group %0;" :: "n"(N) : "memory");
}
__device__ __forceinline__ void ldmat4(uint32_t& r0, uint32_t& r1, uint32_t& r2,
                                       uint32_t& r3, uint32_t addr) {
    asm volatile("ldmatrix.sync.aligned.m8n8.x4.shared.b16 {%0,%1,%2,%3}, [%4];"
                 : "=r"(r0), "=r"(r1), "=r"(r2), "=r"(r3) : "r"(addr));
}
__device__ __forceinline__ void mma_f16(float* d, const uint32_t* a, const uint32_t* b) {
    asm volatile(
        "mma.sync.aligned.m16n8k16.row.col.f32.f16.f16.f32 "
        "{%0,%1,%2,%3}, {%4,%5,%6,%7}, {%8,%9}, {%0,%1,%2,%3};"
        : "+f"(d[0]), "+f"(d[1]), "+f"(d[2]), "+f"(d[3])
        : "r"(a[0]), "r"(a[1]), "r"(a[2]), "r"(a[3]), "r"(b[0]), "r"(b[1]));
}

// argmax key: monotone float encoding, ~index for smaller-index-wins on ties
static __device__ __forceinline__ unsigned long long packKey(float v, int n) {
    unsigned u = __float_as_uint(v);
    u = (u & 0x80000000u) ? ~u : (u | 0x80000000u);
    return ((unsigned long long)u << 32) | (unsigned)(~n);
}

// pack float4 -> fp16x4 (uint2)
static __device__ __forceinline__ uint2 f4_to_h4(float4 v) {
    __half h0 = __float2half(v.x), h1 = __float2half(v.y);
    __half h2 = __float2half(v.z), h3 = __float2half(v.w);
    uint2 r;
    r.x = (uint32_t)__half_as_ushort(h0) | ((uint32_t)__half_as_ushort(h1) << 16);
    r.y = (uint32_t)__half_as_ushort(h2) | ((uint32_t)__half_as_ushort(h3) << 16);
    return r;
}

// ---------------- K1: fused prep ------------------------------------------
// Blocks [0, NVB): emb fp16 convert + row inv-norm; 1 warp per 2 rows,
//   8 front-batched LDG.128 (MLP=8), 4 STG.128 stores, layout-correct:
//   dst uint4 j holds src float4 {2j, 2j+1}.
// Blocks [NVB, NVB+NB): per-batch |grad| sums -> top-k mask -> masked stats
__global__ __launch_bounds__(256) void k_prep(const float* __restrict__ emb,
                                              const float* __restrict__ grad) {
    const int tid = threadIdx.x, lane = tid & 31, w = tid >> 5;
    if (blockIdx.x < NVB) {
        const int r0 = blockIdx.x * ROWS_PER_BLK + w * 2;  // warp's first row
        const int r1 = r0 + 1;
        const bool l0 = r0 < NV, l1 = r1 < NV;
        const float4* s0 = (const float4*)(emb + (size_t)r0 * NE);
        const float4* s1 = (const float4*)(emb + (size_t)r1 * NE);
        float4 a0, a1, a2, a3, b0, b1, b2, b3;  // 8 independent loads
        const float4 z = make_float4(0.f, 0.f, 0.f, 0.f);
        if (l0) {
            a0 = __ldg(s0 + 2 * lane);      a1 = __ldg(s0 + 2 * lane + 1);
            a2 = __ldg(s0 + 2 * lane + 64); a3 = __ldg(s0 + 2 * lane + 65);
        } else { a0 = a1 = a2 = a3 = z; }
        if (l1) {
            b0 = __ldg(s1 + 2 * lane);      b1 = __ldg(s1 + 2 * lane + 1);
            b2 = __ldg(s1 + 2 * lane + 64); b3 = __ldg(s1 + 2 * lane + 65);
        } else { b0 = b1 = b2 = b3 = z; }

        // dst uint4 index j covers src float4 {2j, 2j+1}
        uint4* d0 = (uint4*)(d_embH + (size_t)r0 * NE);
        uint4* d1 = (uint4*)(d_embH + (size_t)r1 * NE);
        uint2 p0 = f4_to_h4(a0), p1 = f4_to_h4(a1);
        uint2 p2 = f4_to_h4(a2), p3 = f4_to_h4(a3);
        d0[lane]      = make_uint4(p0.x, p0.y, p1.x, p1.y);
        d0[lane + 32] = make_uint4(p2.x, p2.y, p3.x, p3.y);
        uint2 q0 = f4_to_h4(b0), q1 = f4_to_h4(b1);
        uint2 q2 = f4_to_h4(b2), q3 = f4_to_h4(b3);
        d1[lane]      = make_uint4(q0.x, q0.y, q1.x, q1.y);
        d1[lane + 32] = make_uint4(q2.x, q2.y, q3.x, q3.y);

        float acc0 = a0.x*a0.x + a0.y*a0.y + a0.z*a0.z + a0.w*a0.w
                   + a1.x*a1.x + a1.y*a1.y + a1.z*a1.z + a1.w*a1.w
                   + a2.x*a2.x + a2.y*a2.y + a2.z*a2.z + a2.w*a2.w
                   + a3.x*a3.x + a3.y*a3.y + a3.z*a3.z + a3.w*a3.w;
        float acc1 = b0.x*b0.x + b0.y*b0.y + b0.z*b0.z + b0.w*b0.w
                   + b1.x*b1.x + b1.y*b1.y + b1.z*b1.z + b1.w*b1.w
                   + b2.x*b2.x + b2.y*b2.y + b2.z*b2.z + b2.w*b2.w
                   + b3.x*b3.x + b3.y*b3.y + b3.z*b3.z + b3.w*b3.w;
        #pragma unroll
        for (int o = 16; o > 0; o >>= 1) {
            acc0 += __shfl_down_sync(0xffffffffu, acc0, o);
            acc1 += __shfl_down_sync(0xffffffffu, acc1, o);
        }
        if (lane == 0) {
            if (l0) d_tinv[r0] = 1.f / fmaxf(sqrtf(acc0), COS_EPS);
            if (l1) d_tinv[r1] = 1.f / fmaxf(sqrtf(acc1), COS_EPS);
        }
    } else {
        const int b = blockIdx.x - NVB;
        __shared__ float s_absg[NS];
        __shared__ int s_msk[NS];
        __shared__ double s_d[16];
        // pass 1: warp w handles tokens w, w+8, ... (8 tokens each)
        for (int tok = w; tok < NS; tok += 8) {
            const float4* p = (const float4*)(grad + (size_t)(b * NS + tok) * NE);
            float s = 0.f;
            #pragma unroll 4
            for (int i = lane; i < NE / 4; i += 32) {
                float4 v = p[i];
                s += fabsf(v.x) + fabsf(v.y) + fabsf(v.z) + fabsf(v.w);
            }
            #pragma unroll
            for (int o = 16; o > 0; o >>= 1) s += __shfl_down_sync(0xffffffffu, s, o);
            if (lane == 0) s_absg[tok] = s;
        }
        __syncthreads();
        // top-k mask by rank count (stable ties)
        if (tid < NS) {
            float me = s_absg[tid];
            int rank = 0;
            #pragma unroll 8
            for (int j = 0; j < NS; j++)
                rank += (s_absg[j] > me) || (s_absg[j] == me && j < tid);
            int mk = (rank < KSEL) ? 1 : 0;
            s_msk[tid] = mk;
            d_mask[b * NS + tid] = mk;
        }
        __syncthreads();
        // pass 2: masked sum / sumsq (L2-hot re-read, double accum)
        double s = 0.0, s2 = 0.0;
        for (int tok = w; tok < NS; tok += 8) {
            if (!s_msk[tok]) continue;
            const float4* p = (const float4*)(grad + (size_t)(b * NS + tok) * NE);
            #pragma unroll 4
            for (int i = lane; i < NE / 4; i += 32) {
                float4 v = p[i];
                double x;
                x = v.x; s += x; s2 += x * x;
                x = v.y; s += x; s2 += x * x;
                x = v.z; s += x; s2 += x * x;
                x = v.w; s += x; s2 += x * x;
            }
        }
        #pragma unroll
        for (int o = 16; o > 0; o >>= 1) {
            s  += __shfl_down_sync(0xffffffffu, s,  o);
            s2 += __shfl_down_sync(0xffffffffu, s2, o);
        }
        if (lane == 0) { s_d[w] = s; s_d[8 + w] = s2; }
        __syncthreads();
        if (tid == 0) {
            double ts = 0.0, ts2 = 0.0;
            #pragma unroll
            for (int i = 0; i < 8; i++) { ts += s_d[i]; ts2 += s_d[8 + i]; }
            d_bsum[b] = ts;
            d_bsumsq[b] = ts2;
        }
    }
}

// ---------------- K2: perturb + inv norm + fp16 store + bounds ------------
__global__ void k_perturb(const int* __restrict__ utt,
                          const float* __restrict__ emb,
                          const float* __restrict__ grad) {
    __shared__ float s_bounds[2];
    __shared__ float sh[4];
    const int tid = threadIdx.x, lane = tid & 31, w = tid >> 5;
    const int t = blockIdx.x;
    // redundant per-block bounds computation from 32 batch partials
    if (w == 0) {
        double s = d_bsum[lane], s2 = d_bsumsq[lane];
        #pragma unroll
        for (int o = 16; o > 0; o >>= 1) {
            s  += __shfl_down_sync(0xffffffffu, s,  o);
            s2 += __shfl_down_sync(0xffffffffu, s2, o);
        }
        if (lane == 0) {
            double n = (double)NB * KSEL * NE;
            double mean = s / n;
            double var = (s2 - n * mean * mean) / (n - 1.0);
            double sd = sqrt(var);
            s_bounds[0] = (float)(mean - sd * STD_MULT);
            s_bounds[1] = (float)(mean + sd * STD_MULT);
            d_best[t] = 0ull;
        }
    }
    __syncthreads();
    const float lb = s_bounds[0], ub = s_bounds[1];
    const int u = utt[t];
    const int m = d_mask[t];
    const float* erow = emb + (size_t)u * NE;
    const float* grow = grad + (size_t)t * NE;
    __half* hrow = d_pertH + (size_t)t * NE;
    float acc = 0.f;
    for (int e = tid; e < NE; e += blockDim.x) {
        float ev = erow[e];
        float dg = grow[e];
        float p = ev;
        if (m && (dg < lb || dg > ub))
            p += (dg > 0.f) ? EPS_ATK : ((dg < 0.f) ? -EPS_ATK : 0.f);
        hrow[e] = __float2half(p);
        acc += p * p;
    }
    #pragma unroll
    for (int o = 16; o > 0; o >>= 1) acc += __shfl_down_sync(0xffffffffu, acc, o);
    if (lane == 0) sh[w] = acc;
    __syncthreads();
    if (tid == 0) {
        float s = sh[0] + sh[1] + sh[2] + sh[3];
        d_pinv[t] = 1.f / fmaxf(sqrtf(s), COS_EPS);
    }
}

// ---------------- K3: HMMA fp16 GEMM (R10-proven 2-stage) + epilogue ------
#define PLANE 16384
#define STG_BYTES (2*PLANE)   // 32KB per stage

__global__ __launch_bounds__(256, 2) void k_gemm(float* __restrict__ simOut,
                                                 int doArgmax) {
    extern __shared__ char dsm[];
    __shared__ float s_tinv[TC_N];
    __shared__ float s_pinv[TC_M];

    const int tid = threadIdx.x;
    const int wid = tid >> 5;
    const int lane = tid & 31;
    const int warp_m = wid & 3;        // 4 row groups of 32
    const int warp_n = wid >> 2;       // 2 col groups of 64
    const int col0 = blockIdx.x * TC_N;
    const int row0 = blockIdx.y * TC_M;

    if (tid < TC_M) s_pinv[tid] = d_pinv[row0 + tid];
    if (tid < TC_N) {
        int c = col0 + tid;
        s_tinv[tid] = (c < NV) ? d_tinv[c] : 0.f;
    }

    const uint32_t smemBase = smem_u32(dsm);

    auto loadStage = [&](int ch, int buf) {
        const int k0 = ch * KCH;
        uint32_t sb = smemBase + buf * STG_BYTES;
        #pragma unroll
        for (int i = 0; i < 4; i++) {
            int q = i * 256 + tid;
            int r = q >> 3, c = q & 7;
            uint32_t dst = sb + r * 128 + ((c ^ (r & 7)) << 4);
            cp_async16(dst,         d_pertH + (size_t)(row0 + r) * NE + k0 + c * 8);
            cp_async16(dst + PLANE, d_embH  + (size_t)(col0 + r) * NE + k0 + c * 8);
        }
    };

    float acc[2][8][4];
    #pragma unroll
    for (int i = 0; i < 2; i++)
        #pragma unroll
        for (int j = 0; j < 8; j++)
            #pragma unroll
            for (int k = 0; k < 4; k++) acc[i][j][k] = 0.f;

    const int aRowIn = lane & 15;
    const int aSel = lane >> 4;
    const int bRowIn = (lane & 7) + ((lane >> 4) << 3);
    const int bSel = (lane >> 3) & 1;

    loadStage(0, 0); cp_commit();
    loadStage(1, 1); cp_commit();

    for (int ch = 0; ch < NCHUNK; ch++) {
        if (ch < NCHUNK - 1) cp_wait<1>(); else cp_wait<0>();
        __syncthreads();
        const uint32_t sb = smemBase + (ch & 1) * STG_BYTES;

        #pragma unroll
        for (int ks = 0; ks < 4; ks++) {
            uint32_t Ah[2][4], Bh[4][4];
            #pragma unroll
            for (int im = 0; im < 2; im++) {
                int row = warp_m * 32 + im * 16 + aRowIn;
                uint32_t off = row * 128 + (((ks * 2 + aSel) ^ (row & 7)) << 4);
                ldmat4(Ah[im][0], Ah[im][1], Ah[im][2], Ah[im][3], sb + off);
            }
            #pragma unroll
            for (int jn = 0; jn < 4; jn++) {
                int nr = warp_n * 64 + jn * 16 + bRowIn;
                uint32_t off = nr * 128 + (((ks * 2 + bSel) ^ (nr & 7)) << 4);
                ldmat4(Bh[jn][0], Bh[jn][1], Bh[jn][2], Bh[jn][3], sb + PLANE + off);
            }
            #pragma unroll
            for (int im = 0; im < 2; im++)
                #pragma unroll
                for (int jn = 0; jn < 4; jn++) {
                    mma_f16(acc[im][2 * jn],     Ah[im], &Bh[jn][0]);
                    mma_f16(acc[im][2 * jn + 1], Ah[im], &Bh[jn][2]);
                }
        }
        __syncthreads();
        if (ch + 2 < NCHUNK) { loadStage(ch + 2, ch & 1); cp_commit(); }
    }

    // ---- register-direct epilogue: scale, scalar streaming stores, argmax
    // (scalar STG.32 only: row base simOut + r*NV has 4B alignment since NV
    //  is odd — a float2 store here traps with misaligned address)
    const int rb = lane >> 2, cb = (lane & 3) * 2;
    #pragma unroll
    for (int im = 0; im < 2; im++) {
        #pragma unroll
        for (int kh = 0; kh < 2; kh++) {
            const int r = warp_m * 32 + im * 16 + rb + kh * 8;
            const float pi = s_pinv[r];
            float* orow = simOut + (size_t)(row0 + r) * NV;
            float bv = -1e30f;
            int bn = -1;
            #pragma unroll
            for (int jn = 0; jn < 8; jn++) {
                const int c = warp_n * 64 + jn * 8 + cb;
                const int gc = col0 + c;
                float v0 = acc[im][jn][kh * 2]     * pi * s_tinv[c];
                float v1 = acc[im][jn][kh * 2 + 1] * pi * s_tinv[c + 1];
                if (gc < NV) {
                    __stcs(orow + gc, v0);
                    if (v0 > bv) { bv = v0; bn = gc; }
                }
                if (gc + 1 < NV) {
                    __stcs(orow + gc + 1, v1);
                    if (v1 > bv) { bv = v1; bn = gc + 1; }
                }
            }
            if (doArgmax) {
                unsigned long long key = (bn >= 0) ? packKey(bv, bn) : 0ull;
                unsigned long long o1 = __shfl_xor_sync(0xffffffffu, key, 1);
                if (o1 > key) key = o1;
                unsigned long long o2 = __shfl_xor_sync(0xffffffffu, key, 2);
                if (o2 > key) key = o2;
                if ((lane & 3) == 0 && key)
                    atomicMax(&d_best[row0 + r], key);
            }
        }
    }
}

// ---------------- K4: decode fused argmax ---------------------------------
__global__ void k_decode(float* __restrict__ nnOut) {
    int t = blockIdx.x * blockDim.x + threadIdx.x;
    if (t < NTOK) nnOut[t] = (float)(~(unsigned)(d_best[t] & 0xFFFFFFFFull));
}

// ---------------- launch ---------------------------------------------------
extern "C" void kernel_launch(void* const* d_in, const int* in_sizes, int n_in,
                              void* d_out, int out_size) {
    const int* utt = (const int*)d_in[0];     // [B,S] int32
    const float* emb = (const float*)d_in[1]; // [V,E] fp32
    const float* grad = (const float*)d_in[2];// [B,S,E] fp32
    float* out = (float*)d_out;

    float* nnOut = nullptr;
    float* simOut = out;
    if (out_size == NTOK * (NV + 1)) {        // tuple order: nn_idx, then sim
        nnOut = out;
        simOut = out + NTOK;
    }

    k_prep<<<NVB + NB, 256>>>(emb, grad);
    k_perturb<<<NTOK, 128>>>(utt, emb, grad);

    const int dynSmem = 2 * STG_BYTES;        // 64KB
    static int attrSet = 0;
    if (!attrSet) {
        cudaFuncSetAttribute(k_gemm, cudaFuncAttributeMaxDynamicSharedMemorySize, dynSmem);
        attrSet = 1;
    }
    dim3 g(NBLK, NTOK / TC_M);
    k_gemm<<<g, 256, dynSmem>>>(simOut, nnOut != nullptr);

    if (nnOut) k_decode<<<(NTOK + 255) / 256, 256>>>(nnOut);
}

// round 15
// speedup vs baseline: 1.2440x; 1.0439x over previous
#include <cuda_runtime.h>
#include <cuda_fp16.h>
#include <math.h>
#include <stdint.h>

#define NB 32
#define NS 64
#define NE 512
#define NV 50257
#define NVP 50304             // NV padded to 128
#define NTOK (NB*NS)          // 2048
#define KSEL (NS/2)           // 32
#define EPS_ATK 0.4f
#define STD_MULT 3.0
#define COS_EPS 1e-8f

// GEMM tile config
#define TC_M 128
#define TC_N 128
#define KCH 64
#define NCHUNK (NE / KCH)     // 8
#define NBLK (NVP / TC_N)     // 393
#define ROWS_PER_BLK 16       // 8 warps x 2 rows
#define NVB (NVP / ROWS_PER_BLK)   // 3144 emb-convert blocks

// ---------------- scratch (device globals; no allocation allowed) ----------
__device__ __half d_pertH[NTOK*NE];      // 2 MB
__device__ __half d_embH[NVP*NE];        // 51.5 MB
__device__ int    d_mask[NTOK];
__device__ float  d_pinv[NTOK];
__device__ float  d_tinv[NV];
__device__ double d_bsum[NB];
__device__ double d_bsumsq[NB];
__device__ unsigned long long d_best[NTOK];

// ---------------- PTX helpers (baseline ISA only) ---------------------------
__device__ __forceinline__ uint32_t smem_u32(const void* p) {
    uint32_t a;
    asm("{ .reg .u64 t; cvta.to.shared.u64 t, %1; cvt.u32.u64 %0, t; }"
        : "=r"(a) : "l"(p));
    return a;
}
__device__ __forceinline__ void cp_async16(uint32_t dst, const void* src) {
    asm volatile("cp.async.cg.shared.global [%0], [%1], 16;"
                 :: "r"(dst), "l"(src) : "memory");
}
__device__ __forceinline__ void cp_commit() {
    asm volatile("cp.async.commit_group;" ::: "memory");
}
template<int N> __device__ __forceinline__ void cp_wait() {
    asm volatile("cp.async.wait_group %0;" :: "n"(N) : "memory");
}
__device__ __forceinline__ void ldmat4(uint32_t& r0, uint32_t& r1, uint32_t& r2,
                                       uint32_t& r3, uint32_t addr) {
    asm volatile("ldmatrix.sync.aligned.m8n8.x4.shared.b16 {%0,%1,%2,%3}, [%4];"
                 : "=r"(r0), "=r"(r1), "=r"(r2), "=r"(r3) : "r"(addr));
}
__device__ __forceinline__ void mma_f16(float* d, const uint32_t* a, const uint32_t* b) {
    asm volatile(
        "mma.sync.aligned.m16n8k16.row.col.f32.f16.f16.f32 "
        "{%0,%1,%2,%3}, {%4,%5,%6,%7}, {%8,%9}, {%0,%1,%2,%3};"
        : "+f"(d[0]), "+f"(d[1]), "+f"(d[2]), "+f"(d[3])
        : "r"(a[0]), "r"(a[1]), "r"(a[2]), "r"(a[3]), "r"(b[0]), "r"(b[1]));
}

// argmax key: monotone float encoding, ~index for smaller-index-wins on ties
static __device__ __forceinline__ unsigned long long packKey(float v, int n) {
    unsigned u = __float_as_uint(v);
    u = (u & 0x80000000u) ? ~u : (u | 0x80000000u);
    return ((unsigned long long)u << 32) | (unsigned)(~n);
}

// pack float4 -> fp16x4 (uint2)
static __device__ __forceinline__ uint2 f4_to_h4(float4 v) {
    __half h0 = __float2half(v.x), h1 = __float2half(v.y);
    __half h2 = __float2half(v.z), h3 = __float2half(v.w);
    uint2 r;
    r.x = (uint32_t)__half_as_ushort(h0) | ((uint32_t)__half_as_ushort(h1) << 16);
    r.y = (uint32_t)__half_as_ushort(h2) | ((uint32_t)__half_as_ushort(h3) << 16);
    return r;
}

// ---------------- K1: fused prep ------------------------------------------
// Blocks [0, NB): per-batch |grad| sums -> top-k mask -> masked stats
//   (FIRST in the grid so they launch in wave 1 and overlap the emb convert)
// Blocks [NB, NB+NVB): emb fp16 convert + row inv-norm; 1 warp per 2 rows,
//   8 front-batched LDG.128 (MLP=8), 4 STG.128; dst uint4 j = src f4 {2j,2j+1}.
__global__ __launch_bounds__(256) void k_prep(const float* __restrict__ emb,
                                              const float* __restrict__ grad) {
    const int tid = threadIdx.x, lane = tid & 31, w = tid >> 5;
    if (blockIdx.x >= NB) {
        const int blk = blockIdx.x - NB;
        const int r0 = blk * ROWS_PER_BLK + w * 2;  // warp's first row
        const int r1 = r0 + 1;
        const bool l0 = r0 < NV, l1 = r1 < NV;
        const float4* s0 = (const float4*)(emb + (size_t)r0 * NE);
        const float4* s1 = (const float4*)(emb + (size_t)r1 * NE);
        float4 a0, a1, a2, a3, b0, b1, b2, b3;  // 8 independent loads
        const float4 z = make_float4(0.f, 0.f, 0.f, 0.f);
        if (l0) {
            a0 = __ldg(s0 + 2 * lane);      a1 = __ldg(s0 + 2 * lane + 1);
            a2 = __ldg(s0 + 2 * lane + 64); a3 = __ldg(s0 + 2 * lane + 65);
        } else { a0 = a1 = a2 = a3 = z; }
        if (l1) {
            b0 = __ldg(s1 + 2 * lane);      b1 = __ldg(s1 + 2 * lane + 1);
            b2 = __ldg(s1 + 2 * lane + 64); b3 = __ldg(s1 + 2 * lane + 65);
        } else { b0 = b1 = b2 = b3 = z; }

        // dst uint4 index j covers src float4 {2j, 2j+1}
        uint4* d0 = (uint4*)(d_embH + (size_t)r0 * NE);
        uint4* d1 = (uint4*)(d_embH + (size_t)r1 * NE);
        uint2 p0 = f4_to_h4(a0), p1 = f4_to_h4(a1);
        uint2 p2 = f4_to_h4(a2), p3 = f4_to_h4(a3);
        d0[lane]      = make_uint4(p0.x, p0.y, p1.x, p1.y);
        d0[lane + 32] = make_uint4(p2.x, p2.y, p3.x, p3.y);
        uint2 q0 = f4_to_h4(b0), q1 = f4_to_h4(b1);
        uint2 q2 = f4_to_h4(b2), q3 = f4_to_h4(b3);
        d1[lane]      = make_uint4(q0.x, q0.y, q1.x, q1.y);
        d1[lane + 32] = make_uint4(q2.x, q2.y, q3.x, q3.y);

        float acc0 = a0.x*a0.x + a0.y*a0.y + a0.z*a0.z + a0.w*a0.w
                   + a1.x*a1.x + a1.y*a1.y + a1.z*a1.z + a1.w*a1.w
                   + a2.x*a2.x + a2.y*a2.y + a2.z*a2.z + a2.w*a2.w
                   + a3.x*a3.x + a3.y*a3.y + a3.z*a3.z + a3.w*a3.w;
        float acc1 = b0.x*b0.x + b0.y*b0.y + b0.z*b0.z + b0.w*b0.w
                   + b1.x*b1.x + b1.y*b1.y + b1.z*b1.z + b1.w*b1.w
                   + b2.x*b2.x + b2.y*b2.y + b2.z*b2.z + b2.w*b2.w
                   + b3.x*b3.x + b3.y*b3.y + b3.z*b3.z + b3.w*b3.w;
        #pragma unroll
        for (int o = 16; o > 0; o >>= 1) {
            acc0 += __shfl_down_sync(0xffffffffu, acc0, o);
            acc1 += __shfl_down_sync(0xffffffffu, acc1, o);
        }
        if (lane == 0) {
            if (l0) d_tinv[r0] = 1.f / fmaxf(sqrtf(acc0), COS_EPS);
            if (l1) d_tinv[r1] = 1.f / fmaxf(sqrtf(acc1), COS_EPS);
        }
    } else {
        const int b = blockIdx.x;
        __shared__ float s_absg[NS];
        __shared__ int s_msk[NS];
        __shared__ double s_d[16];
        // pass 1: warp w handles tokens w, w+8, ... (8 tokens each)
        for (int tok = w; tok < NS; tok += 8) {
            const float4* p = (const float4*)(grad + (size_t)(b * NS + tok) * NE);
            float s = 0.f;
            #pragma unroll 4
            for (int i = lane; i < NE / 4; i += 32) {
                float4 v = p[i];
                s += fabsf(v.x) + fabsf(v.y) + fabsf(v.z) + fabsf(v.w);
            }
            #pragma unroll
            for (int o = 16; o > 0; o >>= 1) s += __shfl_down_sync(0xffffffffu, s, o);
            if (lane == 0) s_absg[tok] = s;
        }
        __syncthreads();
        // top-k mask by rank count (stable ties)
        if (tid < NS) {
            float me = s_absg[tid];
            int rank = 0;
            #pragma unroll 8
            for (int j = 0; j < NS; j++)
                rank += (s_absg[j] > me) || (s_absg[j] == me && j < tid);
            int mk = (rank < KSEL) ? 1 : 0;
            s_msk[tid] = mk;
            d_mask[b * NS + tid] = mk;
        }
        __syncthreads();
        // pass 2: masked sum / sumsq (L2-hot re-read, double accum)
        double s = 0.0, s2 = 0.0;
        for (int tok = w; tok < NS; tok += 8) {
            if (!s_msk[tok]) continue;
            const float4* p = (const float4*)(grad + (size_t)(b * NS + tok) * NE);
            #pragma unroll 4
            for (int i = lane; i < NE / 4; i += 32) {
                float4 v = p[i];
                double x;
                x = v.x; s += x; s2 += x * x;
                x = v.y; s += x; s2 += x * x;
                x = v.z; s += x; s2 += x * x;
                x = v.w; s += x; s2 += x * x;
            }
        }
        #pragma unroll
        for (int o = 16; o > 0; o >>= 1) {
            s  += __shfl_down_sync(0xffffffffu, s,  o);
            s2 += __shfl_down_sync(0xffffffffu, s2, o);
        }
        if (lane == 0) { s_d[w] = s; s_d[8 + w] = s2; }
        __syncthreads();
        if (tid == 0) {
            double ts = 0.0, ts2 = 0.0;
            #pragma unroll
            for (int i = 0; i < 8; i++) { ts += s_d[i]; ts2 += s_d[8 + i]; }
            d_bsum[b] = ts;
            d_bsumsq[b] = ts2;
        }
    }
}

// ---------------- K2: perturb + inv norm + fp16 store + bounds ------------
// 128 threads, one float4 per thread from erow/grow (vectorized).
__global__ void k_perturb(const int* __restrict__ utt,
                          const float* __restrict__ emb,
                          const float* __restrict__ grad) {
    __shared__ float s_bounds[2];
    __shared__ float sh[4];
    const int tid = threadIdx.x, lane = tid & 31, w = tid >> 5;
    const int t = blockIdx.x;
    // redundant per-block bounds computation from 32 batch partials
    if (w == 0) {
        double s = d_bsum[lane], s2 = d_bsumsq[lane];
        #pragma unroll
        for (int o = 16; o > 0; o >>= 1) {
            s  += __shfl_down_sync(0xffffffffu, s,  o);
            s2 += __shfl_down_sync(0xffffffffu, s2, o);
        }
        if (lane == 0) {
            double n = (double)NB * KSEL * NE;
            double mean = s / n;
            double var = (s2 - n * mean * mean) / (n - 1.0);
            double sd = sqrt(var);
            s_bounds[0] = (float)(mean - sd * STD_MULT);
            s_bounds[1] = (float)(mean + sd * STD_MULT);
            d_best[t] = 0ull;
        }
    }
    __syncthreads();
    const float lb = s_bounds[0], ub = s_bounds[1];
    const int u = utt[t];
    const int m = d_mask[t];
    const float4 ev = __ldg((const float4*)(emb + (size_t)u * NE) + tid);
    const float4 gv = __ldg((const float4*)(grad + (size_t)t * NE) + tid);
    float p[4] = {ev.x, ev.y, ev.z, ev.w};
    const float g[4] = {gv.x, gv.y, gv.z, gv.w};
    #pragma unroll
    for (int i = 0; i < 4; i++) {
        if (m && (g[i] < lb || g[i] > ub))
            p[i] += (g[i] > 0.f) ? EPS_ATK : ((g[i] < 0.f) ? -EPS_ATK : 0.f);
    }
    ((uint2*)(d_pertH + (size_t)t * NE))[tid] =
        f4_to_h4(make_float4(p[0], p[1], p[2], p[3]));
    float acc = p[0]*p[0] + p[1]*p[1] + p[2]*p[2] + p[3]*p[3];
    #pragma unroll
    for (int o = 16; o > 0; o >>= 1) acc += __shfl_down_sync(0xffffffffu, acc, o);
    if (lane == 0) sh[w] = acc;
    __syncthreads();
    if (tid == 0) {
        float s = sh[0] + sh[1] + sh[2] + sh[3];
        d_pinv[t] = 1.f / fmaxf(sqrtf(s), COS_EPS);
    }
}

// ---------------- K3: HMMA fp16 GEMM (R10-proven 2-stage) + epilogue ------
#define PLANE 16384
#define STG_BYTES (2*PLANE)   // 32KB per stage

__global__ __launch_bounds__(256, 2) void k_gemm(float* __restrict__ simOut,
                                                 int doArgmax) {
    extern __shared__ char dsm[];
    __shared__ float s_tinv[TC_N];
    __shared__ float s_pinv[TC_M];

    const int tid = threadIdx.x;
    const int wid = tid >> 5;
    const int lane = tid & 31;
    const int warp_m = wid & 3;        // 4 row groups of 32
    const int warp_n = wid >> 2;       // 2 col groups of 64
    const int col0 = blockIdx.x * TC_N;
    const int row0 = blockIdx.y * TC_M;

    if (tid < TC_M) s_pinv[tid] = d_pinv[row0 + tid];
    if (tid < TC_N) {
        int c = col0 + tid;
        s_tinv[tid] = (c < NV) ? d_tinv[c] : 0.f;
    }

    const uint32_t smemBase = smem_u32(dsm);

    auto loadStage = [&](int ch, int buf) {
        const int k0 = ch * KCH;
        uint32_t sb = smemBase + buf * STG_BYTES;
        #pragma unroll
        for (int i = 0; i < 4; i++) {
            int q = i * 256 + tid;
            int r = q >> 3, c = q & 7;
            uint32_t dst = sb + r * 128 + ((c ^ (r & 7)) << 4);
            cp_async16(dst,         d_pertH + (size_t)(row0 + r) * NE + k0 + c * 8);
            cp_async16(dst + PLANE, d_embH  + (size_t)(col0 + r) * NE + k0 + c * 8);
        }
    };

    float acc[2][8][4];
    #pragma unroll
    for (int i = 0; i < 2; i++)
        #pragma unroll
        for (int j = 0; j < 8; j++)
            #pragma unroll
            for (int k = 0; k < 4; k++) acc[i][j][k] = 0.f;

    const int aRowIn = lane & 15;
    const int aSel = lane >> 4;
    const int bRowIn = (lane & 7) + ((lane >> 4) << 3);
    const int bSel = (lane >> 3) & 1;

    loadStage(0, 0); cp_commit();
    loadStage(1, 1); cp_commit();

    for (int ch = 0; ch < NCHUNK; ch++) {
        if (ch < NCHUNK - 1) cp_wait<1>(); else cp_wait<0>();
        __syncthreads();
        const uint32_t sb = smemBase + (ch & 1) * STG_BYTES;

        #pragma unroll
        for (int ks = 0; ks < 4; ks++) {
            uint32_t Ah[2][4], Bh[4][4];
            #pragma unroll
            for (int im = 0; im < 2; im++) {
                int row = warp_m * 32 + im * 16 + aRowIn;
                uint32_t off = row * 128 + (((ks * 2 + aSel) ^ (row & 7)) << 4);
                ldmat4(Ah[im][0], Ah[im][1], Ah[im][2], Ah[im][3], sb + off);
            }
            #pragma unroll
            for (int jn = 0; jn < 4; jn++) {
                int nr = warp_n * 64 + jn * 16 + bRowIn;
                uint32_t off = nr * 128 + (((ks * 2 + bSel) ^ (nr & 7)) << 4);
                ldmat4(Bh[jn][0], Bh[jn][1], Bh[jn][2], Bh[jn][3], sb + PLANE + off);
            }
            #pragma unroll
            for (int im = 0; im < 2; im++)
                #pragma unroll
                for (int jn = 0; jn < 4; jn++) {
                    mma_f16(acc[im][2 * jn],     Ah[im], &Bh[jn][0]);
                    mma_f16(acc[im][2 * jn + 1], Ah[im], &Bh[jn][2]);
                }
        }
        __syncthreads();
        if (ch + 2 < NCHUNK) { loadStage(ch + 2, ch & 1); cp_commit(); }
    }

    // ---- register-direct epilogue: scale, scalar streaming stores, argmax
    // (scalar STG.32 only: row base simOut + r*NV has 4B alignment since NV
    //  is odd — a float2 store here traps with misaligned address)
    const int rb = lane >> 2, cb = (lane & 3) * 2;
    #pragma unroll
    for (int im = 0; im < 2; im++) {
        #pragma unroll
        for (int kh = 0; kh < 2; kh++) {
            const int r = warp_m * 32 + im * 16 + rb + kh * 8;
            const float pi = s_pinv[r];
            float* orow = simOut + (size_t)(row0 + r) * NV;
            float bv = -1e30f;
            int bn = -1;
            #pragma unroll
            for (int jn = 0; jn < 8; jn++) {
                const int c = warp_n * 64 + jn * 8 + cb;
                const int gc = col0 + c;
                float v0 = acc[im][jn][kh * 2]     * pi * s_tinv[c];
                float v1 = acc[im][jn][kh * 2 + 1] * pi * s_tinv[c + 1];
                if (gc < NV) {
                    __stcs(orow + gc, v0);
                    if (v0 > bv) { bv = v0; bn = gc; }
                }
                if (gc + 1 < NV) {
                    __stcs(orow + gc + 1, v1);
                    if (v1 > bv) { bv = v1; bn = gc + 1; }
                }
            }
            if (doArgmax) {
                unsigned long long key = (bn >= 0) ? packKey(bv, bn) : 0ull;
                unsigned long long o1 = __shfl_xor_sync(0xffffffffu, key, 1);
                if (o1 > key) key = o1;
                unsigned long long o2 = __shfl_xor_sync(0xffffffffu, key, 2);
                if (o2 > key) key = o2;
                if ((lane & 3) == 0 && key)
                    atomicMax(&d_best[row0 + r], key);
            }
        }
    }
}

// ---------------- K4: decode fused argmax ---------------------------------
__global__ void k_decode(float* __restrict__ nnOut) {
    int t = blockIdx.x * blockDim.x + threadIdx.x;
    if (t < NTOK) nnOut[t] = (float)(~(unsigned)(d_best[t] & 0xFFFFFFFFull));
}

// ---------------- launch ---------------------------------------------------
extern "C" void kernel_launch(void* const* d_in, const int* in_sizes, int n_in,
                              void* d_out, int out_size) {
    const int* utt = (const int*)d_in[0];     // [B,S] int32
    const float* emb = (const float*)d_in[1]; // [V,E] fp32
    const float* grad = (const float*)d_in[2];// [B,S,E] fp32
    float* out = (float*)d_out;

    float* nnOut = nullptr;
    float* simOut = out;
    if (out_size == NTOK * (NV + 1)) {        // tuple order: nn_idx, then sim
        nnOut = out;
        simOut = out + NTOK;
    }

    k_prep<<<NB + NVB, 256>>>(emb, grad);
    k_perturb<<<NTOK, 128>>>(utt, emb, grad);

    const int dynSmem = 2 * STG_BYTES;        // 64KB
    static int attrSet = 0;
    if (!attrSet) {
        cudaFuncSetAttribute(k_gemm, cudaFuncAttributeMaxDynamicSharedMemorySize, dynSmem);
        attrSet = 1;
    }
    dim3 g(NBLK, NTOK / TC_M);
    k_gemm<<<g, 256, dynSmem>>>(simOut, nnOut != nullptr);

    if (nnOut) k_decode<<<(NTOK + 255) / 256, 256>>>(nnOut);
}